// round 12
// baseline (speedup 1.0000x reference)
#include <cuda_runtime.h>

#define NB   256
#define NT   1024
#define NS   7
#define NH   64
#define NL   4
#define NOUT 3

#define UQ   8                             // timesteps per pipeline interval
#define NBLK (NT / UQ)                     // 128 timestep-blocks
#define CH   64                            // x-staging chunk (timesteps)
#define XPC  (CH * NS)                     // 448 floats

// packed fp32x2 add — same form as ptx_helpers.cuh ADD_F32X2 (no "+l")
#define ADDX2(out, a, b) \
    asm("add.rn.f32x2 %0, %1, %2;" : "=l"(out) : "l"(a), "l"(b))

typedef unsigned long long ull;

// Global (L1-cached) hidden-layer LUT: [48][16][64] floats = 192 KB.
// Entry [(l*16+g)*16 + p][n] = sum over set bits i of p of
//   w_h[l][n][in_neuron(g,i)]  — same layout/convention as the R6 smem table.
__device__ float g_tblH[48 * 16 * 64];

// Neuron ownership: lane owns neurons (2*lane, 2*lane+1).
// maskA bit lane = spike of neuron 2*lane; maskB = neuron 2*lane+1.
// Group g in [0,8): nibble g of maskA -> inputs {8g, 8g+2, 8g+4, 8g+6}
// Group g in [8,16): nibble g-8 of maskB -> odd counterparts.
__device__ __forceinline__ int in_neuron(int g, int i) {
    return (g < 8) ? (8 * g + 2 * i) : (8 * (g - 8) + 2 * i + 1);
}

// Build g_tblH: grid = 48 (one block per (l,g) slice), 256 threads.
__global__ void build_lut_kernel(const float* __restrict__ w_h)
{
    const int lg = blockIdx.x;
    const int l  = lg >> 4, g = lg & 15;
    const int n  = threadIdx.x & 63;       // output neuron
    const int p0 = threadIdx.x >> 6;       // 4 p-values per thread

    float w[4];
#pragma unroll
    for (int i = 0; i < 4; ++i)
        w[i] = w_h[(size_t)(l * NH + n) * NH + in_neuron(g, i)];

#pragma unroll
    for (int k = 0; k < 4; ++k) {
        const int p = p0 + 4 * k;
        float s = 0.f;
        if (p & 1) s += w[0];
        if (p & 2) s += w[1];
        if (p & 4) s += w[2];
        if (p & 8) s += w[3];
        g_tblH[(size_t)(lg * 16 + p) * 64 + n] = s;
    }
}

// One batch per block, 4 warps = 4 pipeline stages, grid = 256.
// Table reads go through __ldg (L1-resident). ~6 KB smem/block ->
// 2 blocks/SM: independent barrier domains overlap each other's stalls.
__global__ __launch_bounds__(128, 2)
void snn_kernel(const float* __restrict__ x,
                const float* __restrict__ hidden0,
                const float* __restrict__ w1,
                const float* __restrict__ b1,
                const float* __restrict__ w_h,
                const float* __restrict__ b_h,
                const float* __restrict__ w_out,
                const float* __restrict__ b_out,
                float* __restrict__ out_outputs,   // (B,T,OUT)
                float* __restrict__ out_hidden)    // (B,T,L,H)
{
    __shared__ float tblO[16 * 16 * 4];    // output-layer LUT (4 KB)
    __shared__ float xw[XPC];              // x staging (1.75 KB)
    __shared__ uint2 mring[4][2][UQ];      // mask ring

    const int tid  = threadIdx.x;
    const int lane = tid & 31;
    const int wid  = tid >> 5;
    const int b    = blockIdx.x;
    // rotate stage->SMSP mapping so co-resident blocks offset light/heavy
    const int rot   = (b + (b >> 2)) & 3;
    const int stage = (wid + rot) & 3;

    // ---- build output-layer LUT in smem ----
    if (tid < 48) {
        const int o = tid >> 4, g = tid & 15;
        float wo[4];
#pragma unroll
        for (int i = 0; i < 4; ++i)
            wo[i] = w_out[o * NH + in_neuron(g, i)];
#pragma unroll
        for (int p = 0; p < 16; ++p) {
            float s = 0.f;
            if (p & 1) s += wo[0];
            if (p & 2) s += wo[1];
            if (p & 4) s += wo[2];
            if (p & 8) s += wo[3];
            tblO[(g * 16 + p) * 4 + o] = s;
        }
    }
    __syncthreads();

    // ---- per-warp state: this stage's layer membranes (neurons 2lane,2lane+1)
    float ma, mbv;
    {
        const float* h0 = hidden0 + (size_t)b * NT * NL * NH + stage * NH;
        float2 m0 = *reinterpret_cast<const float2*>(h0 + 2 * lane);
        ma = m0.x; mbv = m0.y;
    }

    float w1a[NS], w1b[NS];
    float b1a = 0.f, b1b = 0.f, bo = 0.f, bha = 0.f, bhb = 0.f;
    float xs[14];
    const float* xb = x + (size_t)b * NT * NS;
    const int otc = lane / 3;            // output: timestep-in-block
    const int oo  = lane - 3 * otc;      // output: channel
    if (stage == 0) {
#pragma unroll
        for (int s = 0; s < NS; ++s) {
            w1a[s] = w1[(2 * lane)     * NS + s];
            w1b[s] = w1[(2 * lane + 1) * NS + s];
        }
        b1a = b1[2 * lane];
        b1b = b1[2 * lane + 1];
        bo  = (lane < 24) ? b_out[oo] : 0.0f;
#pragma unroll
        for (int j = 0; j < 14; ++j) xs[j] = xb[j * 32 + lane];
    } else {
        bha = b_h[(stage - 1) * NH + 2 * lane];
        bhb = b_h[(stage - 1) * NH + 2 * lane + 1];
    }

    float* hout = out_hidden  + (size_t)b * NT * NL * NH + stage * NH;
    float* oout = out_outputs + (size_t)b * NT * NOUT;
    // byte base of this stage's GLOBAL LUT slice, pre-offset by lane pair
    const char* tb = reinterpret_cast<const char*>(g_tblH)
        + (size_t)(stage > 0 ? (stage - 1) : 0) * (16 * 16 * 64 * 4) + lane * 8;

    for (int i = 0; i < NBLK + 4; ++i) {
        if (stage == 0) {
            if (i < NBLK) {
                if ((i & 7) == 0) {            // new 64-step x chunk
#pragma unroll
                    for (int j = 0; j < 14; ++j) xw[j * 32 + lane] = xs[j];
                    __syncwarp();
                    const int c = i >> 3;
                    if (c + 1 < NT / CH) {
#pragma unroll
                        for (int j = 0; j < 14; ++j)
                            xs[j] = xb[(c + 1) * XPC + j * 32 + lane];
                    }
                }
#pragma unroll
                for (int tt = 0; tt < UQ; ++tt) {
                    const int t = i * UQ + tt;
                    const float* xt = xw + (t & 63) * NS;
                    float cx = b1a, cy = b1b;
#pragma unroll
                    for (int s = 0; s < NS; ++s) {
                        float xv = xt[s];
                        cx = fmaf(xv, w1a[s], cx);
                        cy = fmaf(xv, w1b[s], cy);
                    }
                    float nx = __fadd_rn(__fmul_rn(0.8f, ma),  cx);
                    float ny = __fadd_rn(__fmul_rn(0.8f, mbv), cy);
                    if (ma  > 1.0f) nx = __fadd_rn(nx, -1.0f);
                    if (mbv > 1.0f) ny = __fadd_rn(ny, -1.0f);
                    ma = nx; mbv = ny;
                    unsigned mA = __ballot_sync(0xffffffffu, nx > 1.0f);
                    unsigned mB = __ballot_sync(0xffffffffu, ny > 1.0f);
                    if (lane == 0) mring[0][i & 1][tt] = make_uint2(mA, mB);
                    *reinterpret_cast<float2*>(
                        hout + (size_t)t * NL * NH + 2 * lane) = make_float2(ma, mbv);
                }
            }
            if (i >= 4) {                      // output layer: block i-4
                const int j2 = i - 4;
                uint2 m3 = make_uint2(0u, 0u);
                if (lane < 24) m3 = mring[3][(i - 1) & 1][otc];
                const unsigned eA = m3.x & 0x0F0F0F0Fu, oA = (m3.x >> 4) & 0x0F0F0F0Fu;
                const unsigned eB = m3.y & 0x0F0F0F0Fu, oB = (m3.y >> 4) & 0x0F0F0F0Fu;
                float oacc = bo;
#pragma unroll
                for (int g = 0; g < 16; ++g) {
                    unsigned src = (g < 8) ? ((g & 1) ? oA : eA)
                                           : ((g & 1) ? oB : eB);
                    unsigned idx = __byte_perm(src, 0, 0x4440 | ((g >> 1) & 3));
                    oacc += tblO[(g * 16 + idx) * 4 + oo];
                }
                if (lane < 24) oout[(size_t)j2 * (UQ * NOUT) + lane] = oacc;
            }
        } else {
            const int jj = i - stage;
            if (jj >= 0 && jj < NBLK) {
                const int par = (i - 1) & 1;
                uint2 mm[UQ];
#pragma unroll
                for (int tt = 0; tt < UQ; ++tt)
                    mm[tt] = mring[stage - 1][par][tt];
#pragma unroll
                for (int tt = 0; tt < UQ; ++tt) {
                    const unsigned eA = mm[tt].x & 0x0F0F0F0Fu;
                    const unsigned oA = (mm[tt].x >> 4) & 0x0F0F0F0Fu;
                    const unsigned eB = mm[tt].y & 0x0F0F0F0Fu;
                    const unsigned oB = (mm[tt].y >> 4) & 0x0F0F0F0Fu;
                    ull a0 = 0ull, a1 = 0ull;
#pragma unroll
                    for (int g = 0; g < 16; ++g) {
                        unsigned src = (g < 8) ? ((g & 1) ? oA : eA)
                                               : ((g & 1) ? oB : eB);
                        unsigned idx = __byte_perm(src, 0, 0x4440 | ((g >> 1) & 3));
                        ull v = __ldg(reinterpret_cast<const ull*>(
                            tb + ((size_t)g << 12) + ((size_t)idx << 8)));
                        if (g & 1) { ull r; ADDX2(r, a1, v); a1 = r; }
                        else       { ull r; ADDX2(r, a0, v); a0 = r; }
                    }
                    ull at; ADDX2(at, a0, a1);
                    float2 av = *reinterpret_cast<float2*>(&at);
                    float cx = av.x + bha;
                    float cy = av.y + bhb;
                    float nx = __fadd_rn(__fmul_rn(0.8f, ma),  cx);
                    float ny = __fadd_rn(__fmul_rn(0.8f, mbv), cy);
                    if (ma  > 1.0f) nx = __fadd_rn(nx, -1.0f);
                    if (mbv > 1.0f) ny = __fadd_rn(ny, -1.0f);
                    ma = nx; mbv = ny;
                    unsigned mA = __ballot_sync(0xffffffffu, nx > 1.0f);
                    unsigned mB = __ballot_sync(0xffffffffu, ny > 1.0f);
                    if (lane == 0)
                        mring[stage][i & 1][tt] = make_uint2(mA, mB);
                    const int t = jj * UQ + tt;
                    *reinterpret_cast<float2*>(
                        hout + (size_t)t * NL * NH + 2 * lane) = make_float2(ma, mbv);
                }
            }
        }
        __syncthreads();   // 128-thread barrier, per-block (decoupled across blocks)
    }
}

// x passthrough: third tuple element of the reference output
__global__ void copy_kernel(const float4* __restrict__ src,
                            float4* __restrict__ dst, int n4)
{
    int i = blockIdx.x * blockDim.x + threadIdx.x;
    if (i < n4) dst[i] = src[i];
}

extern "C" void kernel_launch(void* const* d_in, const int* in_sizes, int n_in,
                              void* d_out, int out_size)
{
    const float* x      = (const float*)d_in[0];
    const float* hidden = (const float*)d_in[1];
    // d_in[2] = prev_obs (unused by reference)
    const float* w1     = (const float*)d_in[3];
    const float* b1     = (const float*)d_in[4];
    const float* w_h    = (const float*)d_in[5];
    const float* b_h    = (const float*)d_in[6];
    const float* w_out  = (const float*)d_in[7];
    const float* b_out  = (const float*)d_in[8];

    float* out         = (float*)d_out;
    float* out_outputs = out;                                    // B*T*OUT
    float* out_hidden  = out_outputs + (size_t)NB * NT * NOUT;   // B*T*L*H
    float* out_x       = out_hidden + (size_t)NB * NT * NL * NH; // B*T*S

    // copy FIRST so ncu (-s 5 -c 1) captures the SNN kernel
    const int n4 = (NB * NT * NS) / 4;
    copy_kernel<<<(n4 + 255) / 256, 256>>>((const float4*)x, (float4*)out_x, n4);

    build_lut_kernel<<<48, 256>>>(w_h);
    snn_kernel<<<NB, 128>>>(x, hidden, w1, b1, w_h, b_h,
                            w_out, b_out, out_outputs, out_hidden);
}

// round 14
// speedup vs baseline: 1.0135x; 1.0135x over previous
#include <cuda_runtime.h>

#define NB   256
#define NT   1024
#define NS   7
#define NH   64
#define NL   4
#define NOUT 3

#define UQ   8                             // timesteps per pipeline interval
#define NBLK (NT / UQ)                     // 128 timestep-blocks
#define CH   64                            // x-staging chunk (timesteps)
#define XPC  (CH * NS)                     // 448 floats
#define TBLH_FLOATS (3 * 16 * 16 * 64)     // 192 KB
#define TBLO_FLOATS (16 * 16 * 4)          // 4 KB
#define XS_FLOATS   (2 * XPC)              // [bat][XPC]
#define SMEM_FLOATS (TBLH_FLOATS + TBLO_FLOATS + XS_FLOATS)
#define SMEM_BYTES  (SMEM_FLOATS * 4 + 2 * 4 * 2 * UQ * 8)

// packed fp32x2 add — same form as ptx_helpers.cuh ADD_F32X2 (no "+l")
#define ADDX2(out, a, b) \
    asm("add.rn.f32x2 %0, %1, %2;" : "=l"(out) : "l"(a), "l"(b))

typedef unsigned long long ull;

// Neuron ownership: lane owns neurons (2*lane, 2*lane+1).
// maskA bit lane = spike of neuron 2*lane; maskB = neuron 2*lane+1.
// Group g in [0,8): nibble g of maskA -> inputs {8g, 8g+2, 8g+4, 8g+6}
// Group g in [8,16): nibble g-8 of maskB -> odd counterparts.
__device__ __forceinline__ int in_neuron(int g, int i) {
    return (g < 8) ? (8 * g + 2 * i) : (8 * (g - 8) + 2 * i + 1);
}

// 16 subset-sum lookups for one (maskA, maskB); tb pre-offset by lane*8.
__device__ __forceinline__ void lut16(unsigned mA, unsigned mB,
                                      const char* tb, float2& out) {
    const unsigned eA = mA & 0x0F0F0F0Fu, oA = (mA >> 4) & 0x0F0F0F0Fu;
    const unsigned eB = mB & 0x0F0F0F0Fu, oB = (mB >> 4) & 0x0F0F0F0Fu;
    ull a0 = 0ull, a1 = 0ull;
#pragma unroll
    for (int g = 0; g < 16; ++g) {
        unsigned src = (g < 8) ? ((g & 1) ? oA : eA)
                               : ((g & 1) ? oB : eB);
        unsigned idx = __byte_perm(src, 0, 0x4440 | ((g >> 1) & 3));
        ull v = *reinterpret_cast<const ull*>(
            tb + ((size_t)g << 12) + ((size_t)idx << 8));
        if (g & 1) { ull r; ADDX2(r, a1, v); a1 = r; }
        else       { ull r; ADDX2(r, a0, v); a0 = r; }
    }
    ull at; ADDX2(at, a0, a1);
    out = *reinterpret_cast<float2*>(&at);
}

// 4 warps per block (one per pipeline stage); each warp carries TWO batches'
// recurrences — two independent dependency chains interleaved by ptxas inside
// one instruction stream (intra-warp latency hiding, zero added instructions).
__global__ __launch_bounds__(128, 1)
void snn_kernel(const float* __restrict__ x,
                const float* __restrict__ hidden0,
                const float* __restrict__ w1,
                const float* __restrict__ b1,
                const float* __restrict__ w_h,
                const float* __restrict__ b_h,
                const float* __restrict__ w_out,
                const float* __restrict__ b_out,
                float* __restrict__ out_outputs,   // (B,T,OUT)
                float* __restrict__ out_hidden)    // (B,T,L,H)
{
    extern __shared__ float smem[];
    float* tblH = smem;                        // [48][16][64]
    float* tblO = smem + TBLH_FLOATS;          // [16][16][4]
    float* xbuf = tblO + TBLO_FLOATS;          // [2][XPC]
    uint2 (*mring)[4][2][UQ] =
        reinterpret_cast<uint2 (*)[4][2][UQ]>(smem + SMEM_FLOATS);

    const int tid   = threadIdx.x;
    const int lane  = tid & 31;
    const int wid   = tid >> 5;
    const int stage = wid;
    const int bb0   = blockIdx.x * 2;
    const int bb1   = bb0 + 1;

    // ---- build LUTs (4 warps stripe the 48 (l,g) slices) ----
    {
        for (int lg = wid; lg < 48; lg += 4) {
            const int l = lg >> 4, g = lg & 15;
            float wa[4], wb[4];
#pragma unroll
            for (int i = 0; i < 4; ++i) {
                const int in = in_neuron(g, i);
                wa[i] = w_h[(size_t)(l * NH + 2 * lane)     * NH + in];
                wb[i] = w_h[(size_t)(l * NH + 2 * lane + 1) * NH + in];
            }
            float* dst = tblH + (size_t)(lg * 16) * 64 + 2 * lane;
#pragma unroll
            for (int p = 0; p < 16; ++p) {
                float sa = 0.f, sb = 0.f;
                if (p & 1) { sa += wa[0]; sb += wb[0]; }
                if (p & 2) { sa += wa[1]; sb += wb[1]; }
                if (p & 4) { sa += wa[2]; sb += wb[2]; }
                if (p & 8) { sa += wa[3]; sb += wb[3]; }
                *reinterpret_cast<float2*>(dst + (size_t)p * 64) =
                    make_float2(sa, sb);
            }
        }
        if (tid < 48) {
            const int o = tid >> 4, g = tid & 15;
            float wo[4];
#pragma unroll
            for (int i = 0; i < 4; ++i)
                wo[i] = w_out[o * NH + in_neuron(g, i)];
#pragma unroll
            for (int p = 0; p < 16; ++p) {
                float s = 0.f;
                if (p & 1) s += wo[0];
                if (p & 2) s += wo[1];
                if (p & 4) s += wo[2];
                if (p & 8) s += wo[3];
                tblO[(g * 16 + p) * 4 + o] = s;
            }
        }
    }
    __syncthreads();

    // ---- membranes for BOTH batches (this stage's layer) ----
    float ma0, mb0, ma1, mb1;
    {
        const float* h0 = hidden0 + (size_t)bb0 * NT * NL * NH + stage * NH;
        const float* h1 = hidden0 + (size_t)bb1 * NT * NL * NH + stage * NH;
        float2 v0 = *reinterpret_cast<const float2*>(h0 + 2 * lane);
        float2 v1 = *reinterpret_cast<const float2*>(h1 + 2 * lane);
        ma0 = v0.x; mb0 = v0.y;
        ma1 = v1.x; mb1 = v1.y;
    }

    float w1a[NS], w1b[NS];                // shared between both batches
    float b1a = 0.f, b1b = 0.f, bo = 0.f, bha = 0.f, bhb = 0.f;
    float xs0[14], xs1[14];
    const float* xg0 = x + (size_t)bb0 * NT * NS;
    const float* xg1 = x + (size_t)bb1 * NT * NS;
    const int otc = lane / 3;              // output: timestep-in-block
    const int oo  = lane - 3 * otc;        // output: channel
    if (stage == 0) {
#pragma unroll
        for (int s = 0; s < NS; ++s) {
            w1a[s] = w1[(2 * lane)     * NS + s];
            w1b[s] = w1[(2 * lane + 1) * NS + s];
        }
        b1a = b1[2 * lane];
        b1b = b1[2 * lane + 1];
        bo  = (lane < 24) ? b_out[oo] : 0.0f;
#pragma unroll
        for (int j = 0; j < 14; ++j) {
            xs0[j] = xg0[j * 32 + lane];
            xs1[j] = xg1[j * 32 + lane];
        }
    } else {
        bha = b_h[(stage - 1) * NH + 2 * lane];
        bhb = b_h[(stage - 1) * NH + 2 * lane + 1];
    }

    float* hout0 = out_hidden  + (size_t)bb0 * NT * NL * NH + stage * NH;
    float* hout1 = out_hidden  + (size_t)bb1 * NT * NL * NH + stage * NH;
    float* oout0 = out_outputs + (size_t)bb0 * NT * NOUT;
    float* oout1 = out_outputs + (size_t)bb1 * NT * NOUT;
    const char* tb = reinterpret_cast<const char*>(
        tblH + (size_t)(stage > 0 ? (stage - 1) : 0) * (16 * 16 * 64)) + lane * 8;

    for (int i = 0; i < NBLK + 4; ++i) {
        if (stage == 0) {
            if (i < NBLK) {
                if ((i & 7) == 0) {            // new 64-step x chunk, both batches
#pragma unroll
                    for (int j = 0; j < 14; ++j) {
                        xbuf[j * 32 + lane]       = xs0[j];
                        xbuf[XPC + j * 32 + lane] = xs1[j];
                    }
                    __syncwarp();
                    const int c = i >> 3;
                    if (c + 1 < NT / CH) {
#pragma unroll
                        for (int j = 0; j < 14; ++j) {
                            xs0[j] = xg0[(c + 1) * XPC + j * 32 + lane];
                            xs1[j] = xg1[(c + 1) * XPC + j * 32 + lane];
                        }
                    }
                }
#pragma unroll
                for (int tt = 0; tt < UQ; ++tt) {
                    const int t = i * UQ + tt;
                    const float* xt0 = xbuf + (t & 63) * NS;
                    const float* xt1 = xbuf + XPC + (t & 63) * NS;
                    float cx0 = b1a, cy0 = b1b, cx1 = b1a, cy1 = b1b;
#pragma unroll
                    for (int s = 0; s < NS; ++s) {
                        float v0 = xt0[s], v1 = xt1[s];
                        cx0 = fmaf(v0, w1a[s], cx0);
                        cy0 = fmaf(v0, w1b[s], cy0);
                        cx1 = fmaf(v1, w1a[s], cx1);
                        cy1 = fmaf(v1, w1b[s], cy1);
                    }
                    float nx0 = __fadd_rn(__fmul_rn(0.8f, ma0), cx0);
                    float ny0 = __fadd_rn(__fmul_rn(0.8f, mb0), cy0);
                    float nx1 = __fadd_rn(__fmul_rn(0.8f, ma1), cx1);
                    float ny1 = __fadd_rn(__fmul_rn(0.8f, mb1), cy1);
                    if (ma0 > 1.0f) nx0 = __fadd_rn(nx0, -1.0f);
                    if (mb0 > 1.0f) ny0 = __fadd_rn(ny0, -1.0f);
                    if (ma1 > 1.0f) nx1 = __fadd_rn(nx1, -1.0f);
                    if (mb1 > 1.0f) ny1 = __fadd_rn(ny1, -1.0f);
                    ma0 = nx0; mb0 = ny0; ma1 = nx1; mb1 = ny1;
                    unsigned mA0 = __ballot_sync(0xffffffffu, nx0 > 1.0f);
                    unsigned mB0 = __ballot_sync(0xffffffffu, ny0 > 1.0f);
                    unsigned mA1 = __ballot_sync(0xffffffffu, nx1 > 1.0f);
                    unsigned mB1 = __ballot_sync(0xffffffffu, ny1 > 1.0f);
                    if (lane == 0) {
                        mring[0][0][i & 1][tt] = make_uint2(mA0, mB0);
                        mring[1][0][i & 1][tt] = make_uint2(mA1, mB1);
                    }
                    *reinterpret_cast<float2*>(
                        hout0 + (size_t)t * NL * NH + 2 * lane) = make_float2(ma0, mb0);
                    *reinterpret_cast<float2*>(
                        hout1 + (size_t)t * NL * NH + 2 * lane) = make_float2(ma1, mb1);
                }
            }
            if (i >= 4) {                      // output layer: block i-4, both batches
                const int j2  = i - 4;
                const int par = (i - 1) & 1;
#pragma unroll
                for (int bat = 0; bat < 2; ++bat) {
                    uint2 m3 = make_uint2(0u, 0u);
                    if (lane < 24) m3 = mring[bat][3][par][otc];
                    const unsigned eA = m3.x & 0x0F0F0F0Fu;
                    const unsigned oA = (m3.x >> 4) & 0x0F0F0F0Fu;
                    const unsigned eB = m3.y & 0x0F0F0F0Fu;
                    const unsigned oB = (m3.y >> 4) & 0x0F0F0F0Fu;
                    float oacc = bo;
#pragma unroll
                    for (int g = 0; g < 16; ++g) {
                        unsigned src = (g < 8) ? ((g & 1) ? oA : eA)
                                               : ((g & 1) ? oB : eB);
                        unsigned idx = __byte_perm(src, 0, 0x4440 | ((g >> 1) & 3));
                        oacc += tblO[(g * 16 + idx) * 4 + oo];
                    }
                    if (lane < 24)
                        (bat ? oout1 : oout0)[(size_t)j2 * (UQ * NOUT) + lane] = oacc;
                }
            }
        } else {
            const int jj = i - stage;
            if (jj >= 0 && jj < NBLK) {
                const int par = (i - 1) & 1;
                uint2 mm0[UQ], mm1[UQ];
#pragma unroll
                for (int tt = 0; tt < UQ; ++tt) {
                    mm0[tt] = mring[0][stage - 1][par][tt];
                    mm1[tt] = mring[1][stage - 1][par][tt];
                }
#pragma unroll
                for (int tt = 0; tt < UQ; ++tt) {
                    float2 s0, s1;                 // two independent LDS batches
                    lut16(mm0[tt].x, mm0[tt].y, tb, s0);
                    lut16(mm1[tt].x, mm1[tt].y, tb, s1);
                    float cx0 = s0.x + bha, cy0 = s0.y + bhb;
                    float cx1 = s1.x + bha, cy1 = s1.y + bhb;
                    float nx0 = __fadd_rn(__fmul_rn(0.8f, ma0), cx0);
                    float ny0 = __fadd_rn(__fmul_rn(0.8f, mb0), cy0);
                    float nx1 = __fadd_rn(__fmul_rn(0.8f, ma1), cx1);
                    float ny1 = __fadd_rn(__fmul_rn(0.8f, mb1), cy1);
                    if (ma0 > 1.0f) nx0 = __fadd_rn(nx0, -1.0f);
                    if (mb0 > 1.0f) ny0 = __fadd_rn(ny0, -1.0f);
                    if (ma1 > 1.0f) nx1 = __fadd_rn(nx1, -1.0f);
                    if (mb1 > 1.0f) ny1 = __fadd_rn(ny1, -1.0f);
                    ma0 = nx0; mb0 = ny0; ma1 = nx1; mb1 = ny1;
                    unsigned mA0 = __ballot_sync(0xffffffffu, nx0 > 1.0f);
                    unsigned mB0 = __ballot_sync(0xffffffffu, ny0 > 1.0f);
                    unsigned mA1 = __ballot_sync(0xffffffffu, nx1 > 1.0f);
                    unsigned mB1 = __ballot_sync(0xffffffffu, ny1 > 1.0f);
                    if (lane == 0) {
                        mring[0][stage][i & 1][tt] = make_uint2(mA0, mB0);
                        mring[1][stage][i & 1][tt] = make_uint2(mA1, mB1);
                    }
                    const int t = jj * UQ + tt;
                    *reinterpret_cast<float2*>(
                        hout0 + (size_t)t * NL * NH + 2 * lane) = make_float2(ma0, mb0);
                    *reinterpret_cast<float2*>(
                        hout1 + (size_t)t * NL * NH + 2 * lane) = make_float2(ma1, mb1);
                }
            }
        }
        __syncthreads();   // orders mask publish -> next-interval consume
    }
}

// x passthrough: third tuple element of the reference output
__global__ void copy_kernel(const float4* __restrict__ src,
                            float4* __restrict__ dst, int n4)
{
    int i = blockIdx.x * blockDim.x + threadIdx.x;
    if (i < n4) dst[i] = src[i];
}

extern "C" void kernel_launch(void* const* d_in, const int* in_sizes, int n_in,
                              void* d_out, int out_size)
{
    const float* x      = (const float*)d_in[0];
    const float* hidden = (const float*)d_in[1];
    // d_in[2] = prev_obs (unused by reference)
    const float* w1     = (const float*)d_in[3];
    const float* b1     = (const float*)d_in[4];
    const float* w_h    = (const float*)d_in[5];
    const float* b_h    = (const float*)d_in[6];
    const float* w_out  = (const float*)d_in[7];
    const float* b_out  = (const float*)d_in[8];

    float* out         = (float*)d_out;
    float* out_outputs = out;                                    // B*T*OUT
    float* out_hidden  = out_outputs + (size_t)NB * NT * NOUT;   // B*T*L*H
    float* out_x       = out_hidden + (size_t)NB * NT * NL * NH; // B*T*S

    // copy FIRST so ncu (-s 5 -c 1) captures the SNN kernel
    const int n4 = (NB * NT * NS) / 4;
    copy_kernel<<<(n4 + 255) / 256, 256>>>((const float4*)x, (float4*)out_x, n4);

    cudaFuncSetAttribute(snn_kernel,
                         cudaFuncAttributeMaxDynamicSharedMemorySize, SMEM_BYTES);
    snn_kernel<<<NB / 2, 128, SMEM_BYTES>>>(x, hidden, w1, b1, w_h, b_h,
                                            w_out, b_out, out_outputs, out_hidden);
}

// round 15
// speedup vs baseline: 1.2012x; 1.1853x over previous
#include <cuda_runtime.h>

#define NB   256
#define NT   1024
#define NS   7
#define NH   64
#define NL   4
#define NOUT 3

#define UQ   8                             // timesteps per pipeline interval
#define NBLK (NT / UQ)                     // 128 timestep-blocks
#define NITER (NBLK + 4)
#define CH   64                            // x-staging chunk (timesteps)
#define XPC  (CH * NS)                     // 448 floats
#define TBLH_FLOATS (3 * 16 * 16 * 64)     // 192 KB
#define TBLO_FLOATS (16 * 16 * 4)          // 4 KB
#define XS_FLOATS   (2 * XPC)
#define SMEM_FLOATS (TBLH_FLOATS + TBLO_FLOATS + XS_FLOATS)
#define MRING_BYTES (2 * 4 * 4 * UQ * 8)   // [bslot][stage][slot4][UQ] uint2 = 2 KB
#define SMEM_BYTES  (SMEM_FLOATS * 4 + MRING_BYTES)

#define ADDX2(out, a, b) \
    asm("add.rn.f32x2 %0, %1, %2;" : "=l"(out) : "l"(a), "l"(b))
// pairwise producer/consumer barrier: exactly 2 warps (64 threads) participate
#define BARSYNC(id) asm volatile("bar.sync %0, 64;" :: "r"(id) : "memory")

typedef unsigned long long ull;

// Neuron ownership: lane owns neurons (2*lane, 2*lane+1).
// maskA bit lane = spike of neuron 2*lane; maskB = neuron 2*lane+1.
// Group g in [0,8): nibble g of maskA -> inputs {8g, 8g+2, 8g+4, 8g+6}
// Group g in [8,16): nibble g-8 of maskB -> odd counterparts.
__device__ __forceinline__ int in_neuron(int g, int i) {
    return (g < 8) ? (8 * g + 2 * i) : (8 * (g - 8) + 2 * i + 1);
}

__global__ __launch_bounds__(256, 1)
void snn_kernel(const float* __restrict__ x,
                const float* __restrict__ hidden0,
                const float* __restrict__ w1,
                const float* __restrict__ b1,
                const float* __restrict__ w_h,
                const float* __restrict__ b_h,
                const float* __restrict__ w_out,
                const float* __restrict__ b_out,
                float* __restrict__ out_outputs,   // (B,T,OUT)
                float* __restrict__ out_hidden)    // (B,T,L,H)
{
    extern __shared__ float smem[];
    float* tblH = smem;                        // [48][16][64]
    float* tblO = smem + TBLH_FLOATS;          // [16][16][4]
    float* xbuf = tblO + TBLO_FLOATS;          // [2][XPC]
    uint2 (*mring)[4][4][UQ] =
        reinterpret_cast<uint2 (*)[4][4][UQ]>(smem + SMEM_FLOATS);

    const int tid   = threadIdx.x;
    const int lane  = tid & 31;
    const int wid   = tid >> 5;
    const int bslot = wid >> 2;
    // rotate stages for bslot1 so heavy stages spread across SMSPs
    const int stage = ((wid & 3) + 2 * bslot) & 3;
    const int eb    = 3 * bslot;               // barrier-id base (ids 1..6)
    const int b     = blockIdx.x * 2 + bslot;

    // ---- build LUTs (8 warps stripe the 48 (l,g) slices) ----
    {
        for (int lg = wid; lg < 48; lg += 8) {
            const int l = lg >> 4, g = lg & 15;
            float wa[4], wb[4];
#pragma unroll
            for (int i = 0; i < 4; ++i) {
                const int in = in_neuron(g, i);
                wa[i] = w_h[(size_t)(l * NH + 2 * lane)     * NH + in];
                wb[i] = w_h[(size_t)(l * NH + 2 * lane + 1) * NH + in];
            }
            float* dst = tblH + (size_t)(lg * 16) * 64 + 2 * lane;
#pragma unroll
            for (int p = 0; p < 16; ++p) {
                float sa = 0.f, sb = 0.f;
                if (p & 1) { sa += wa[0]; sb += wb[0]; }
                if (p & 2) { sa += wa[1]; sb += wb[1]; }
                if (p & 4) { sa += wa[2]; sb += wb[2]; }
                if (p & 8) { sa += wa[3]; sb += wb[3]; }
                *reinterpret_cast<float2*>(dst + (size_t)p * 64) =
                    make_float2(sa, sb);
            }
        }
        if (tid < 48) {
            const int o = tid >> 4, g = tid & 15;
            float wo[4];
#pragma unroll
            for (int i = 0; i < 4; ++i)
                wo[i] = w_out[o * NH + in_neuron(g, i)];
#pragma unroll
            for (int p = 0; p < 16; ++p) {
                float s = 0.f;
                if (p & 1) s += wo[0];
                if (p & 2) s += wo[1];
                if (p & 4) s += wo[2];
                if (p & 8) s += wo[3];
                tblO[(g * 16 + p) * 4 + o] = s;
            }
        }
    }
    __syncthreads();   // barrier 0: LUTs ready

    // ---- per-warp state: this stage's layer membranes (neurons 2lane,2lane+1)
    float ma, mbv;
    {
        const float* h0 = hidden0 + (size_t)b * NT * NL * NH + stage * NH;
        float2 m0 = *reinterpret_cast<const float2*>(h0 + 2 * lane);
        ma = m0.x; mbv = m0.y;
    }

    float w1a[NS], w1b[NS];
    float b1a = 0.f, b1b = 0.f, bo = 0.f, bha = 0.f, bhb = 0.f;
    float xs[14];
    const float* xb = x + (size_t)b * NT * NS;
    float* xw = xbuf + bslot * XPC;
    const int otc = lane / 3;            // output: timestep-in-block
    const int oo  = lane - 3 * otc;      // output: channel
    if (stage == 0) {
#pragma unroll
        for (int s = 0; s < NS; ++s) {
            w1a[s] = w1[(2 * lane)     * NS + s];
            w1b[s] = w1[(2 * lane + 1) * NS + s];
        }
        b1a = b1[2 * lane];
        b1b = b1[2 * lane + 1];
#pragma unroll
        for (int j = 0; j < 14; ++j) xs[j] = xb[j * 32 + lane];
    } else {
        bha = b_h[(stage - 1) * NH + 2 * lane];
        bhb = b_h[(stage - 1) * NH + 2 * lane + 1];
        if (stage == 3) bo = (lane < 24) ? b_out[oo] : 0.0f;
    }

    float* hout = out_hidden  + (size_t)b * NT * NL * NH + stage * NH;
    float* oout = out_outputs + (size_t)b * NT * NOUT;
    const char* tb = reinterpret_cast<const char*>(
        tblH + (size_t)(stage > 0 ? (stage - 1) : 0) * (16 * 16 * 64)) + lane * 8;

    for (int i = 0; i < NITER; ++i) {
        if (stage == 0) {
            // produce edge e1 (top-of-interval: consumer pairs with our PREVIOUS work)
            BARSYNC(1 + eb);
            if (i < NBLK) {
                if ((i & 7) == 0) {            // new 64-step x chunk
#pragma unroll
                    for (int j = 0; j < 14; ++j) xw[j * 32 + lane] = xs[j];
                    __syncwarp();
                    const int c = i >> 3;
                    if (c + 1 < NT / CH) {
#pragma unroll
                        for (int j = 0; j < 14; ++j)
                            xs[j] = xb[(c + 1) * XPC + j * 32 + lane];
                    }
                }
#pragma unroll
                for (int tt = 0; tt < UQ; ++tt) {
                    const int t = i * UQ + tt;
                    const float* xt = xw + (t & 63) * NS;
                    float cx = b1a, cy = b1b;
#pragma unroll
                    for (int s = 0; s < NS; ++s) {
                        float xv = xt[s];
                        cx = fmaf(xv, w1a[s], cx);
                        cy = fmaf(xv, w1b[s], cy);
                    }
                    float nx = __fadd_rn(__fmul_rn(0.8f, ma),  cx);
                    float ny = __fadd_rn(__fmul_rn(0.8f, mbv), cy);
                    if (ma  > 1.0f) nx = __fadd_rn(nx, -1.0f);
                    if (mbv > 1.0f) ny = __fadd_rn(ny, -1.0f);
                    ma = nx; mbv = ny;
                    unsigned mA = __ballot_sync(0xffffffffu, nx > 1.0f);
                    unsigned mB = __ballot_sync(0xffffffffu, ny > 1.0f);
                    if (lane == 0) mring[bslot][0][i & 3][tt] = make_uint2(mA, mB);
                    *reinterpret_cast<float2*>(
                        hout + (size_t)t * NL * NH + 2 * lane) = make_float2(ma, mbv);
                }
            }
        } else {
            BARSYNC(stage + eb);                    // consume edge e_stage
            if (stage <= 2) BARSYNC(stage + 1 + eb);// produce edge e_{stage+1}

            if (stage == 3 && i >= 4) {             // output layer: block i-4
                const int j2 = i - 4;               // reads OWN masks written @i-1
                uint2 m3 = make_uint2(0u, 0u);
                if (lane < 24) m3 = mring[bslot][3][(i - 1) & 3][otc];
                const unsigned eA = m3.x & 0x0F0F0F0Fu, oA = (m3.x >> 4) & 0x0F0F0F0Fu;
                const unsigned eB = m3.y & 0x0F0F0F0Fu, oB = (m3.y >> 4) & 0x0F0F0F0Fu;
                float oacc = bo;
#pragma unroll
                for (int g = 0; g < 16; ++g) {
                    unsigned src = (g < 8) ? ((g & 1) ? oA : eA)
                                           : ((g & 1) ? oB : eB);
                    unsigned idx = __byte_perm(src, 0, 0x4440 | ((g >> 1) & 3));
                    oacc += tblO[(g * 16 + idx) * 4 + oo];
                }
                if (lane < 24) oout[(size_t)j2 * (UQ * NOUT) + lane] = oacc;
            }

            const int jj = i - stage;
            if (jj >= 0 && jj < NBLK) {
                uint2 mm[UQ];
#pragma unroll
                for (int tt = 0; tt < UQ; ++tt)
                    mm[tt] = mring[bslot][stage - 1][(i - 1) & 3][tt];
#pragma unroll
                for (int tt = 0; tt < UQ; ++tt) {
                    const unsigned eA = mm[tt].x & 0x0F0F0F0Fu;
                    const unsigned oA = (mm[tt].x >> 4) & 0x0F0F0F0Fu;
                    const unsigned eB = mm[tt].y & 0x0F0F0F0Fu;
                    const unsigned oB = (mm[tt].y >> 4) & 0x0F0F0F0Fu;
                    ull a0 = 0ull, a1 = 0ull;
#pragma unroll
                    for (int g = 0; g < 16; ++g) {
                        unsigned src = (g < 8) ? ((g & 1) ? oA : eA)
                                               : ((g & 1) ? oB : eB);
                        unsigned idx = __byte_perm(src, 0, 0x4440 | ((g >> 1) & 3));
                        ull v = *reinterpret_cast<const ull*>(
                            tb + ((size_t)g << 12) + ((size_t)idx << 8));
                        if (g & 1) { ull r; ADDX2(r, a1, v); a1 = r; }
                        else       { ull r; ADDX2(r, a0, v); a0 = r; }
                    }
                    ull at; ADDX2(at, a0, a1);
                    float2 av = *reinterpret_cast<float2*>(&at);
                    float cx = av.x + bha;
                    float cy = av.y + bhb;
                    float nx = __fadd_rn(__fmul_rn(0.8f, ma),  cx);
                    float ny = __fadd_rn(__fmul_rn(0.8f, mbv), cy);
                    if (ma  > 1.0f) nx = __fadd_rn(nx, -1.0f);
                    if (mbv > 1.0f) ny = __fadd_rn(ny, -1.0f);
                    ma = nx; mbv = ny;
                    unsigned mA = __ballot_sync(0xffffffffu, nx > 1.0f);
                    unsigned mB = __ballot_sync(0xffffffffu, ny > 1.0f);
                    if (lane == 0)
                        mring[bslot][stage][i & 3][tt] = make_uint2(mA, mB);
                    const int t = jj * UQ + tt;
                    *reinterpret_cast<float2*>(
                        hout + (size_t)t * NL * NH + 2 * lane) = make_float2(ma, mbv);
                }
            }
        }
        // NO global barrier: elastic pairwise pipeline
    }
}

// x passthrough: third tuple element of the reference output
__global__ void copy_kernel(const float4* __restrict__ src,
                            float4* __restrict__ dst, int n4)
{
    int i = blockIdx.x * blockDim.x + threadIdx.x;
    if (i < n4) dst[i] = src[i];
}

extern "C" void kernel_launch(void* const* d_in, const int* in_sizes, int n_in,
                              void* d_out, int out_size)
{
    const float* x      = (const float*)d_in[0];
    const float* hidden = (const float*)d_in[1];
    // d_in[2] = prev_obs (unused by reference)
    const float* w1     = (const float*)d_in[3];
    const float* b1     = (const float*)d_in[4];
    const float* w_h    = (const float*)d_in[5];
    const float* b_h    = (const float*)d_in[6];
    const float* w_out  = (const float*)d_in[7];
    const float* b_out  = (const float*)d_in[8];

    float* out         = (float*)d_out;
    float* out_outputs = out;                                    // B*T*OUT
    float* out_hidden  = out_outputs + (size_t)NB * NT * NOUT;   // B*T*L*H
    float* out_x       = out_hidden + (size_t)NB * NT * NL * NH; // B*T*S

    // copy FIRST so ncu (-s 5 -c 1) captures the SNN kernel
    const int n4 = (NB * NT * NS) / 4;
    copy_kernel<<<(n4 + 255) / 256, 256>>>((const float4*)x, (float4*)out_x, n4);

    cudaFuncSetAttribute(snn_kernel,
                         cudaFuncAttributeMaxDynamicSharedMemorySize, SMEM_BYTES);
    snn_kernel<<<NB / 2, 256, SMEM_BYTES>>>(x, hidden, w1, b1, w_h, b_h,
                                            w_out, b_out, out_outputs, out_hidden);
}

// round 16
// speedup vs baseline: 1.3585x; 1.1309x over previous
#include <cuda_runtime.h>

#define NB   256
#define NT   1024
#define NS   7
#define NH   64
#define NL   4
#define NOUT 3

#define UQ   8                             // timesteps per pipeline interval
#define NBLK (NT / UQ)                     // 128 timestep-blocks
#define CH   64                            // x-staging chunk (timesteps)
#define XPC  (CH * NS)                     // 448 floats
#define TBLH_FLOATS (3 * 16 * 16 * 64)     // 192 KB
#define TBLO_FLOATS (16 * 16 * 4)          // 4 KB
#define XS_FLOATS   (2 * XPC)
#define SMEM_FLOATS (TBLH_FLOATS + TBLO_FLOATS + XS_FLOATS)
#define SMEM_BYTES  (SMEM_FLOATS * 4 + 2 * 4 * 2 * UQ * 8)

// packed fp32x2 add — same form as ptx_helpers.cuh ADD_F32X2 (no "+l")
#define ADDX2(out, a, b) \
    asm("add.rn.f32x2 %0, %1, %2;" : "=l"(out) : "l"(a), "l"(b))

typedef unsigned long long ull;

// Neuron ownership: lane owns neurons (2*lane, 2*lane+1).
// maskA bit lane = spike of neuron 2*lane; maskB = neuron 2*lane+1.
// Group g in [0,8): nibble g of maskA -> inputs {8g, 8g+2, 8g+4, 8g+6}
// Group g in [8,16): nibble g-8 of maskB -> odd counterparts.
__device__ __forceinline__ int in_neuron(int g, int i) {
    return (g < 8) ? (8 * g + 2 * i) : (8 * (g - 8) + 2 * i + 1);
}

__global__ __launch_bounds__(256, 1)
void snn_kernel(const float* __restrict__ x,
                const float* __restrict__ hidden0,
                const float* __restrict__ w1,
                const float* __restrict__ b1,
                const float* __restrict__ w_h,
                const float* __restrict__ b_h,
                const float* __restrict__ w_out,
                const float* __restrict__ b_out,
                float* __restrict__ out_outputs,   // (B,T,OUT)
                float* __restrict__ out_hidden)    // (B,T,L,H)
{
    extern __shared__ float smem[];
    float* tblH = smem;                        // [48][16][64]
    float* tblO = smem + TBLH_FLOATS;          // [16][16][4]
    float* xbuf = tblO + TBLO_FLOATS;          // [2][XPC]
    uint2 (*mring)[4][2][UQ] =
        reinterpret_cast<uint2 (*)[4][2][UQ]>(smem + SMEM_FLOATS);

    const int tid   = threadIdx.x;
    const int lane  = tid & 31;
    const int wid   = tid >> 5;
    const int stage = wid & 3;
    const int bslot = wid >> 2;
    const int b     = blockIdx.x * 2 + bslot;

    // ---- build LUTs (8 warps stripe the 48 (l,g) slices) ----
    {
        for (int lg = wid; lg < 48; lg += 8) {
            const int l = lg >> 4, g = lg & 15;
            float wa[4], wb[4];
#pragma unroll
            for (int i = 0; i < 4; ++i) {
                const int in = in_neuron(g, i);
                wa[i] = w_h[(size_t)(l * NH + 2 * lane)     * NH + in];
                wb[i] = w_h[(size_t)(l * NH + 2 * lane + 1) * NH + in];
            }
            float* dst = tblH + (size_t)(lg * 16) * 64 + 2 * lane;
#pragma unroll
            for (int p = 0; p < 16; ++p) {
                float sa = 0.f, sb = 0.f;
                if (p & 1) { sa += wa[0]; sb += wb[0]; }
                if (p & 2) { sa += wa[1]; sb += wb[1]; }
                if (p & 4) { sa += wa[2]; sb += wb[2]; }
                if (p & 8) { sa += wa[3]; sb += wb[3]; }
                *reinterpret_cast<float2*>(dst + (size_t)p * 64) =
                    make_float2(sa, sb);
            }
        }
        if (tid < 48) {
            const int o = tid >> 4, g = tid & 15;
            float wo[4];
#pragma unroll
            for (int i = 0; i < 4; ++i)
                wo[i] = w_out[o * NH + in_neuron(g, i)];
#pragma unroll
            for (int p = 0; p < 16; ++p) {
                float s = 0.f;
                if (p & 1) s += wo[0];
                if (p & 2) s += wo[1];
                if (p & 4) s += wo[2];
                if (p & 8) s += wo[3];
                tblO[(g * 16 + p) * 4 + o] = s;
            }
        }
    }
    __syncthreads();

    // ---- per-warp state: this stage's layer membranes (neurons 2lane,2lane+1)
    float ma, mbv;
    {
        const float* h0 = hidden0 + (size_t)b * NT * NL * NH + stage * NH;
        float2 m0 = *reinterpret_cast<const float2*>(h0 + 2 * lane);
        ma = m0.x; mbv = m0.y;
    }

    float w1a[NS], w1b[NS];
    float b1a = 0.f, b1b = 0.f, bo = 0.f, bha = 0.f, bhb = 0.f;
    float xs[14];
    const float* xb = x + (size_t)b * NT * NS;
    float* xw = xbuf + bslot * XPC;
    const int otc = lane / 3;            // output: timestep-in-block
    const int oo  = lane - 3 * otc;      // output: channel
    if (stage == 0) {
#pragma unroll
        for (int s = 0; s < NS; ++s) {
            w1a[s] = w1[(2 * lane)     * NS + s];
            w1b[s] = w1[(2 * lane + 1) * NS + s];
        }
        b1a = b1[2 * lane];
        b1b = b1[2 * lane + 1];
        bo  = (lane < 24) ? b_out[oo] : 0.0f;
#pragma unroll
        for (int j = 0; j < 14; ++j) xs[j] = xb[j * 32 + lane];
    } else {
        bha = b_h[(stage - 1) * NH + 2 * lane];
        bhb = b_h[(stage - 1) * NH + 2 * lane + 1];
    }

    float* hout = out_hidden  + (size_t)b * NT * NL * NH + stage * NH;
    float* oout = out_outputs + (size_t)b * NT * NOUT;
    // byte base of this stage's LUT slice, pre-offset by lane pair
    const char* tb = reinterpret_cast<const char*>(
        tblH + (size_t)(stage > 0 ? (stage - 1) : 0) * (16 * 16 * 64)) + lane * 8;

    for (int i = 0; i < NBLK + 4; ++i) {
        if (stage == 0) {
            if (i < NBLK) {
                if ((i & 7) == 0) {            // new 64-step x chunk
#pragma unroll
                    for (int j = 0; j < 14; ++j) xw[j * 32 + lane] = xs[j];
                    __syncwarp();
                    const int c = i >> 3;
                    if (c + 1 < NT / CH) {
#pragma unroll
                        for (int j = 0; j < 14; ++j)
                            xs[j] = xb[(c + 1) * XPC + j * 32 + lane];
                    }
                }
#pragma unroll
                for (int tt = 0; tt < UQ; ++tt) {
                    const int t = i * UQ + tt;
                    const float* xt = xw + (t & 63) * NS;
                    float cx = b1a, cy = b1b;
#pragma unroll
                    for (int s = 0; s < NS; ++s) {
                        float xv = xt[s];
                        cx = fmaf(xv, w1a[s], cx);
                        cy = fmaf(xv, w1b[s], cy);
                    }
                    float nx = __fadd_rn(__fmul_rn(0.8f, ma),  cx);
                    float ny = __fadd_rn(__fmul_rn(0.8f, mbv), cy);
                    if (ma  > 1.0f) nx = __fadd_rn(nx, -1.0f);
                    if (mbv > 1.0f) ny = __fadd_rn(ny, -1.0f);
                    ma = nx; mbv = ny;
                    unsigned mA = __ballot_sync(0xffffffffu, nx > 1.0f);
                    unsigned mB = __ballot_sync(0xffffffffu, ny > 1.0f);
                    if (lane == 0) mring[bslot][0][i & 1][tt] = make_uint2(mA, mB);
                    *reinterpret_cast<float2*>(
                        hout + (size_t)t * NL * NH + 2 * lane) = make_float2(ma, mbv);
                }
            }
            if (i >= 4) {                      // output layer: block i-4
                const int j2 = i - 4;
                uint2 m3 = make_uint2(0u, 0u);
                if (lane < 24) m3 = mring[bslot][3][(i - 1) & 1][otc];
                const unsigned eA = m3.x & 0x0F0F0F0Fu, oA = (m3.x >> 4) & 0x0F0F0F0Fu;
                const unsigned eB = m3.y & 0x0F0F0F0Fu, oB = (m3.y >> 4) & 0x0F0F0F0Fu;
                float oacc = bo;
#pragma unroll
                for (int g = 0; g < 16; ++g) {
                    unsigned src = (g < 8) ? ((g & 1) ? oA : eA)
                                           : ((g & 1) ? oB : eB);
                    unsigned idx = __byte_perm(src, 0, 0x4440 | ((g >> 1) & 3));
                    oacc += tblO[(g * 16 + idx) * 4 + oo];
                }
                if (lane < 24) oout[(size_t)j2 * (UQ * NOUT) + lane] = oacc;
            }
        } else {
            const int jj = i - stage;
            if (jj >= 0 && jj < NBLK) {
                const int par = (i - 1) & 1;
                // ---- hoist ALL mask prep (4 words per step) ----
                unsigned pm[UQ][4];
#pragma unroll
                for (int tt = 0; tt < UQ; ++tt) {
                    uint2 mm = mring[bslot][stage - 1][par][tt];
                    pm[tt][0] = mm.x & 0x0F0F0F0Fu;
                    pm[tt][1] = (mm.x >> 4) & 0x0F0F0F0Fu;
                    pm[tt][2] = mm.y & 0x0F0F0F0Fu;
                    pm[tt][3] = (mm.y >> 4) & 0x0F0F0F0Fu;
                }
                // ---- software pipeline: load step tt+1 while summing step tt
                ull v[2][16];
#pragma unroll
                for (int g = 0; g < 16; ++g) {
                    unsigned src = pm[0][(g < 8) ? (g & 1) : (2 | (g & 1))];
                    unsigned idx = __byte_perm(src, 0, 0x4440 | ((g >> 1) & 3));
                    v[0][g] = *reinterpret_cast<const ull*>(
                        tb + ((size_t)g << 12) + ((size_t)idx << 8));
                }
#pragma unroll
                for (int tt = 0; tt < UQ; ++tt) {
                    const int cur = tt & 1, nxt = cur ^ 1;
                    if (tt + 1 < UQ) {
#pragma unroll
                        for (int g = 0; g < 16; ++g) {
                            unsigned src = pm[tt + 1][(g < 8) ? (g & 1) : (2 | (g & 1))];
                            unsigned idx = __byte_perm(src, 0, 0x4440 | ((g >> 1) & 3));
                            v[nxt][g] = *reinterpret_cast<const ull*>(
                                tb + ((size_t)g << 12) + ((size_t)idx << 8));
                        }
                    }
                    // ---- 4-level binary-tree reduction (depth 4, 15 ADDX2)
                    ull s8[8];
#pragma unroll
                    for (int k = 0; k < 8; ++k)
                        ADDX2(s8[k], v[cur][2 * k], v[cur][2 * k + 1]);
                    ull s4[4];
#pragma unroll
                    for (int k = 0; k < 4; ++k)
                        ADDX2(s4[k], s8[2 * k], s8[2 * k + 1]);
                    ull s2a, s2b, at;
                    ADDX2(s2a, s4[0], s4[1]);
                    ADDX2(s2b, s4[2], s4[3]);
                    ADDX2(at, s2a, s2b);
                    float2 av = *reinterpret_cast<float2*>(&at);
                    float cx = av.x + bha;
                    float cy = av.y + bhb;
                    float nx = __fadd_rn(__fmul_rn(0.8f, ma),  cx);
                    float ny = __fadd_rn(__fmul_rn(0.8f, mbv), cy);
                    if (ma  > 1.0f) nx = __fadd_rn(nx, -1.0f);
                    if (mbv > 1.0f) ny = __fadd_rn(ny, -1.0f);
                    ma = nx; mbv = ny;
                    unsigned mA = __ballot_sync(0xffffffffu, nx > 1.0f);
                    unsigned mB = __ballot_sync(0xffffffffu, ny > 1.0f);
                    if (lane == 0)
                        mring[bslot][stage][i & 1][tt] = make_uint2(mA, mB);
                    const int t = jj * UQ + tt;
                    *reinterpret_cast<float2*>(
                        hout + (size_t)t * NL * NH + 2 * lane) = make_float2(ma, mbv);
                }
            }
        }
        __syncthreads();   // orders mask publish -> next-interval consume
    }
}

// x passthrough: third tuple element of the reference output
__global__ void copy_kernel(const float4* __restrict__ src,
                            float4* __restrict__ dst, int n4)
{
    int i = blockIdx.x * blockDim.x + threadIdx.x;
    if (i < n4) dst[i] = src[i];
}

extern "C" void kernel_launch(void* const* d_in, const int* in_sizes, int n_in,
                              void* d_out, int out_size)
{
    const float* x      = (const float*)d_in[0];
    const float* hidden = (const float*)d_in[1];
    // d_in[2] = prev_obs (unused by reference)
    const float* w1     = (const float*)d_in[3];
    const float* b1     = (const float*)d_in[4];
    const float* w_h    = (const float*)d_in[5];
    const float* b_h    = (const float*)d_in[6];
    const float* w_out  = (const float*)d_in[7];
    const float* b_out  = (const float*)d_in[8];

    float* out         = (float*)d_out;
    float* out_outputs = out;                                    // B*T*OUT
    float* out_hidden  = out_outputs + (size_t)NB * NT * NOUT;   // B*T*L*H
    float* out_x       = out_hidden + (size_t)NB * NT * NL * NH; // B*T*S

    // copy FIRST so ncu (-s 5 -c 1) captures the SNN kernel
    const int n4 = (NB * NT * NS) / 4;
    copy_kernel<<<(n4 + 255) / 256, 256>>>((const float4*)x, (float4*)out_x, n4);

    cudaFuncSetAttribute(snn_kernel,
                         cudaFuncAttributeMaxDynamicSharedMemorySize, SMEM_BYTES);
    snn_kernel<<<NB / 2, 256, SMEM_BYTES>>>(x, hidden, w1, b1, w_h, b_h,
                                            w_out, b_out, out_outputs, out_hidden);
}

// round 17
// speedup vs baseline: 1.4254x; 1.0492x over previous
#include <cuda_runtime.h>

#define NB   256
#define NT   1024
#define NS   7
#define NH   64
#define NL   4
#define NOUT 3

#define UQ   16                            // timesteps per pipeline interval
#define NBLK (NT / UQ)                     // 64 timestep-blocks
#define NITER (NBLK + 4)
#define CH   64                            // x-staging chunk = 4 intervals
#define XPC  (CH * NS)                     // 448 floats
#define TBLH_FLOATS (3 * 16 * 16 * 64)     // 192 KB
#define TBLO_FLOATS (16 * 16 * 4)          // 4 KB
#define XS_FLOATS   (2 * XPC)
#define SMEM_FLOATS (TBLH_FLOATS + TBLO_FLOATS + XS_FLOATS)
#define SMEM_BYTES  (SMEM_FLOATS * 4 + 2 * 4 * 2 * UQ * 8)

// packed fp32x2 add — same form as ptx_helpers.cuh ADD_F32X2 (no "+l")
#define ADDX2(out, a, b) \
    asm("add.rn.f32x2 %0, %1, %2;" : "=l"(out) : "l"(a), "l"(b))

typedef unsigned long long ull;

// Neuron ownership: lane owns neurons (2*lane, 2*lane+1).
// maskA bit lane = spike of neuron 2*lane; maskB = neuron 2*lane+1.
// Group g in [0,8): nibble g of maskA -> inputs {8g, 8g+2, 8g+4, 8g+6}
// Group g in [8,16): nibble g-8 of maskB -> odd counterparts.
__device__ __forceinline__ int in_neuron(int g, int i) {
    return (g < 8) ? (8 * g + 2 * i) : (8 * (g - 8) + 2 * i + 1);
}

// issue 16 prefetch loads for one step's masks into v[16]
__device__ __forceinline__ void lut_load16(uint2 mm, const char* tb, ull* v) {
    const unsigned eA = mm.x & 0x0F0F0F0Fu, oA = (mm.x >> 4) & 0x0F0F0F0Fu;
    const unsigned eB = mm.y & 0x0F0F0F0Fu, oB = (mm.y >> 4) & 0x0F0F0F0Fu;
#pragma unroll
    for (int g = 0; g < 16; ++g) {
        unsigned src = (g < 8) ? ((g & 1) ? oA : eA)
                               : ((g & 1) ? oB : eB);
        unsigned idx = __byte_perm(src, 0, 0x4440 | ((g >> 1) & 3));
        v[g] = *reinterpret_cast<const ull*>(
            tb + ((size_t)g << 12) + ((size_t)idx << 8));
    }
}

__global__ __launch_bounds__(256, 1)
void snn_kernel(const float* __restrict__ x,
                const float* __restrict__ hidden0,
                const float* __restrict__ w1,
                const float* __restrict__ b1,
                const float* __restrict__ w_h,
                const float* __restrict__ b_h,
                const float* __restrict__ w_out,
                const float* __restrict__ b_out,
                float* __restrict__ out_outputs,   // (B,T,OUT)
                float* __restrict__ out_hidden)    // (B,T,L,H)
{
    extern __shared__ float smem[];
    float* tblH = smem;                        // [48][16][64]
    float* tblO = smem + TBLH_FLOATS;          // [16][16][4]
    float* xbuf = tblO + TBLO_FLOATS;          // [2][XPC]
    uint2 (*mring)[4][2][UQ] =
        reinterpret_cast<uint2 (*)[4][2][UQ]>(smem + SMEM_FLOATS);

    const int tid   = threadIdx.x;
    const int lane  = tid & 31;
    const int wid   = tid >> 5;
    const int stage = wid & 3;
    const int bslot = wid >> 2;
    const int b     = blockIdx.x * 2 + bslot;

    // ---- build LUTs (8 warps stripe the 48 (l,g) slices) ----
    {
        for (int lg = wid; lg < 48; lg += 8) {
            const int l = lg >> 4, g = lg & 15;
            float wa[4], wb[4];
#pragma unroll
            for (int i = 0; i < 4; ++i) {
                const int in = in_neuron(g, i);
                wa[i] = w_h[(size_t)(l * NH + 2 * lane)     * NH + in];
                wb[i] = w_h[(size_t)(l * NH + 2 * lane + 1) * NH + in];
            }
            float* dst = tblH + (size_t)(lg * 16) * 64 + 2 * lane;
#pragma unroll
            for (int p = 0; p < 16; ++p) {
                float sa = 0.f, sb = 0.f;
                if (p & 1) { sa += wa[0]; sb += wb[0]; }
                if (p & 2) { sa += wa[1]; sb += wb[1]; }
                if (p & 4) { sa += wa[2]; sb += wb[2]; }
                if (p & 8) { sa += wa[3]; sb += wb[3]; }
                *reinterpret_cast<float2*>(dst + (size_t)p * 64) =
                    make_float2(sa, sb);
            }
        }
        if (tid < 48) {
            const int o = tid >> 4, g = tid & 15;
            float wo[4];
#pragma unroll
            for (int i = 0; i < 4; ++i)
                wo[i] = w_out[o * NH + in_neuron(g, i)];
#pragma unroll
            for (int p = 0; p < 16; ++p) {
                float s = 0.f;
                if (p & 1) s += wo[0];
                if (p & 2) s += wo[1];
                if (p & 4) s += wo[2];
                if (p & 8) s += wo[3];
                tblO[(g * 16 + p) * 4 + o] = s;
            }
        }
    }
    __syncthreads();

    // ---- per-warp state: this stage's layer membranes (neurons 2lane,2lane+1)
    float ma, mbv;
    {
        const float* h0 = hidden0 + (size_t)b * NT * NL * NH + stage * NH;
        float2 m0 = *reinterpret_cast<const float2*>(h0 + 2 * lane);
        ma = m0.x; mbv = m0.y;
    }

    float w1a[NS], w1b[NS];
    float b1a = 0.f, b1b = 0.f, bha = 0.f, bhb = 0.f;
    float bo0 = 0.f, bo1 = 0.f;
    float xs[14];
    const float* xb = x + (size_t)b * NT * NS;
    float* xw = xbuf + bslot * XPC;
    // output mapping, two passes: out index = lane, lane+32  (48 outs/interval)
    const int otc0 = lane / 3,        oo0 = lane - 3 * otc0;
    const int otc1 = (lane + 32) / 3, oo1 = (lane + 32) - 3 * otc1;
    if (stage == 0) {
#pragma unroll
        for (int s = 0; s < NS; ++s) {
            w1a[s] = w1[(2 * lane)     * NS + s];
            w1b[s] = w1[(2 * lane + 1) * NS + s];
        }
        b1a = b1[2 * lane];
        b1b = b1[2 * lane + 1];
        bo0 = b_out[oo0];
        bo1 = (lane < 16) ? b_out[oo1] : 0.0f;
#pragma unroll
        for (int j = 0; j < 14; ++j) xs[j] = xb[j * 32 + lane];
    } else {
        bha = b_h[(stage - 1) * NH + 2 * lane];
        bhb = b_h[(stage - 1) * NH + 2 * lane + 1];
    }

    float* hout = out_hidden  + (size_t)b * NT * NL * NH + stage * NH;
    float* oout = out_outputs + (size_t)b * NT * NOUT;
    const char* tb = reinterpret_cast<const char*>(
        tblH + (size_t)(stage > 0 ? (stage - 1) : 0) * (16 * 16 * 64)) + lane * 8;

    for (int i = 0; i < NITER; ++i) {
        if (stage == 0) {
            if (i < NBLK) {
                if ((i & 3) == 0) {            // new 64-step x chunk
#pragma unroll
                    for (int j = 0; j < 14; ++j) xw[j * 32 + lane] = xs[j];
                    __syncwarp();
                    const int c = i >> 2;
                    if (c + 1 < NT / CH) {
#pragma unroll
                        for (int j = 0; j < 14; ++j)
                            xs[j] = xb[(c + 1) * XPC + j * 32 + lane];
                    }
                }
#pragma unroll
                for (int tt = 0; tt < UQ; ++tt) {
                    const int t = i * UQ + tt;
                    const float* xt = xw + (t & 63) * NS;
                    float cx = b1a, cy = b1b;
#pragma unroll
                    for (int s = 0; s < NS; ++s) {
                        float xv = xt[s];
                        cx = fmaf(xv, w1a[s], cx);
                        cy = fmaf(xv, w1b[s], cy);
                    }
                    float nx = __fadd_rn(__fmul_rn(0.8f, ma),  cx);
                    float ny = __fadd_rn(__fmul_rn(0.8f, mbv), cy);
                    if (ma  > 1.0f) nx = __fadd_rn(nx, -1.0f);
                    if (mbv > 1.0f) ny = __fadd_rn(ny, -1.0f);
                    ma = nx; mbv = ny;
                    unsigned mA = __ballot_sync(0xffffffffu, nx > 1.0f);
                    unsigned mB = __ballot_sync(0xffffffffu, ny > 1.0f);
                    if (lane == 0) mring[bslot][0][i & 1][tt] = make_uint2(mA, mB);
                    *reinterpret_cast<float2*>(
                        hout + (size_t)t * NL * NH + 2 * lane) = make_float2(ma, mbv);
                }
            }
            if (i >= 4) {                      // output layer: block i-4, 2 passes
                const int j2  = i - 4;
                const int par = (i - 1) & 1;
#pragma unroll
                for (int pass = 0; pass < 2; ++pass) {
                    const int otc = pass ? otc1 : otc0;
                    const int oo  = pass ? oo1  : oo0;
                    const bool act = pass ? (lane < 16) : true;
                    uint2 m3 = make_uint2(0u, 0u);
                    if (act) m3 = mring[bslot][3][par][otc];
                    const unsigned eA = m3.x & 0x0F0F0F0Fu;
                    const unsigned oA = (m3.x >> 4) & 0x0F0F0F0Fu;
                    const unsigned eB = m3.y & 0x0F0F0F0Fu;
                    const unsigned oB = (m3.y >> 4) & 0x0F0F0F0Fu;
                    float oacc = pass ? bo1 : bo0;
#pragma unroll
                    for (int g = 0; g < 16; ++g) {
                        unsigned src = (g < 8) ? ((g & 1) ? oA : eA)
                                               : ((g & 1) ? oB : eB);
                        unsigned idx = __byte_perm(src, 0, 0x4440 | ((g >> 1) & 3));
                        oacc += tblO[(g * 16 + idx) * 4 + oo];
                    }
                    if (act)
                        oout[(size_t)j2 * (UQ * NOUT) + 32 * pass + lane] = oacc;
                }
            }
        } else {
            const int jj = i - stage;
            if (jj >= 0 && jj < NBLK) {
                const int par = (i - 1) & 1;
                // hoist all masks for this block (registers, off critical path)
                uint2 mm[UQ];
#pragma unroll
                for (int tt = 0; tt < UQ; ++tt)
                    mm[tt] = mring[bslot][stage - 1][par][tt];
                // software pipeline: step tt+1's loads issue before tt's sum
                ull v[2][16];
                lut_load16(mm[0], tb, v[0]);
#pragma unroll
                for (int tt = 0; tt < UQ; ++tt) {
                    const int cur = tt & 1, nxt = cur ^ 1;
                    if (tt + 1 < UQ) lut_load16(mm[tt + 1], tb, v[nxt]);
                    // 4-level binary-tree reduction (depth 4, 15 ADDX2)
                    ull s8[8];
#pragma unroll
                    for (int k = 0; k < 8; ++k)
                        ADDX2(s8[k], v[cur][2 * k], v[cur][2 * k + 1]);
                    ull s4[4];
#pragma unroll
                    for (int k = 0; k < 4; ++k)
                        ADDX2(s4[k], s8[2 * k], s8[2 * k + 1]);
                    ull s2a, s2b, at;
                    ADDX2(s2a, s4[0], s4[1]);
                    ADDX2(s2b, s4[2], s4[3]);
                    ADDX2(at, s2a, s2b);
                    float2 av = *reinterpret_cast<float2*>(&at);
                    float cx = av.x + bha;
                    float cy = av.y + bhb;
                    float nx = __fadd_rn(__fmul_rn(0.8f, ma),  cx);
                    float ny = __fadd_rn(__fmul_rn(0.8f, mbv), cy);
                    if (ma  > 1.0f) nx = __fadd_rn(nx, -1.0f);
                    if (mbv > 1.0f) ny = __fadd_rn(ny, -1.0f);
                    ma = nx; mbv = ny;
                    unsigned mA = __ballot_sync(0xffffffffu, nx > 1.0f);
                    unsigned mB = __ballot_sync(0xffffffffu, ny > 1.0f);
                    if (lane == 0)
                        mring[bslot][stage][i & 1][tt] = make_uint2(mA, mB);
                    const int t = jj * UQ + tt;
                    *reinterpret_cast<float2*>(
                        hout + (size_t)t * NL * NH + 2 * lane) = make_float2(ma, mbv);
                }
            }
        }
        __syncthreads();   // orders mask publish -> next-interval consume
    }
}

// x passthrough: third tuple element of the reference output
__global__ void copy_kernel(const float4* __restrict__ src,
                            float4* __restrict__ dst, int n4)
{
    int i = blockIdx.x * blockDim.x + threadIdx.x;
    if (i < n4) dst[i] = src[i];
}

extern "C" void kernel_launch(void* const* d_in, const int* in_sizes, int n_in,
                              void* d_out, int out_size)
{
    const float* x      = (const float*)d_in[0];
    const float* hidden = (const float*)d_in[1];
    // d_in[2] = prev_obs (unused by reference)
    const float* w1     = (const float*)d_in[3];
    const float* b1     = (const float*)d_in[4];
    const float* w_h    = (const float*)d_in[5];
    const float* b_h    = (const float*)d_in[6];
    const float* w_out  = (const float*)d_in[7];
    const float* b_out  = (const float*)d_in[8];

    float* out         = (float*)d_out;
    float* out_outputs = out;                                    // B*T*OUT
    float* out_hidden  = out_outputs + (size_t)NB * NT * NOUT;   // B*T*L*H
    float* out_x       = out_hidden + (size_t)NB * NT * NL * NH; // B*T*S

    // copy FIRST so ncu (-s 5 -c 1) captures the SNN kernel
    const int n4 = (NB * NT * NS) / 4;
    copy_kernel<<<(n4 + 255) / 256, 256>>>((const float4*)x, (float4*)out_x, n4);

    cudaFuncSetAttribute(snn_kernel,
                         cudaFuncAttributeMaxDynamicSharedMemorySize, SMEM_BYTES);
    snn_kernel<<<NB / 2, 256, SMEM_BYTES>>>(x, hidden, w1, b1, w_h, b_h,
                                            w_out, b_out, out_outputs, out_hidden);
}